// round 15
// baseline (speedup 1.0000x reference)
#include <cuda_runtime.h>

#define NUM_EDGES   500000
#define SIZE1       80000
#define SIZE2       80000
#define BATCH       8

// Batch-minor copy of x: xt[s*8 + b]. 2.56 MB, L2-resident during edge kernel.
__device__ float g_xt[SIZE1 * BATCH];

// Full batch-minor accumulator scratch, 2 copies (edge-parity) for contention.
// q[copy][s*8 + b]. One edge's 32 outputs = one 128B-aligned line.
#define QCOPY   (SIZE2 * 8)
__device__ float g_q[2 * QCOPY];

// ---------------------------------------------------------------------------
// K1 (prep): zero scratch (float4); transpose x[b,s] -> xt[s,b].
// ---------------------------------------------------------------------------
__global__ void __launch_bounds__(256)
prep_kernel(const float* __restrict__ x) {
    int idx = blockIdx.x * blockDim.x + threadIdx.x;

    if (idx < (2 * QCOPY) / 4) {
        reinterpret_cast<float4*>(g_q)[idx] = make_float4(0.f, 0.f, 0.f, 0.f);
    }

    if (idx < SIZE1 * 2) {
        int s = idx >> 1;
        int h = idx & 1;           // batch half: 0 -> b=0..3, 1 -> b=4..7
        float4 v;
        v.x = __ldg(&x[(4 * h + 0) * SIZE1 + s]);
        v.y = __ldg(&x[(4 * h + 1) * SIZE1 + s]);
        v.z = __ldg(&x[(4 * h + 2) * SIZE1 + s]);
        v.w = __ldg(&x[(4 * h + 3) * SIZE1 + s]);
        *reinterpret_cast<float4*>(g_xt + (size_t)s * 8 + 4 * h) = v;
    }
}

// ---------------------------------------------------------------------------
// K2: edge kernel. 4 lanes per edge, 8 edges per warp. Lane (g, t).
//  - v row i=t via dense cooperative weight load (512B/instr)
//  - x: lane t loads row i=t of the 128B x-block as 2 float4 (2 line-touches
//    per edge), then 4x4 float2 butterfly transpose to get x[i][2t,2t+1]
//  - accumulate all j for batches 2t,2t+1 via shfl of v rows
//  - transpose accumulators so lane t owns output row j=t (all 8 batches),
//    emit 2 red.v4 into the edge's single 128B scratch line
// ---------------------------------------------------------------------------
__global__ void __launch_bounds__(256)
spmm_edge_kernel(const float4* __restrict__ w_mean4,
                 const float4* __restrict__ w_lv4,
                 const float4* __restrict__ eps_w4,
                 const int* __restrict__ rows,
                 const int* __restrict__ cols) {
    const unsigned FULL = 0xffffffffu;
    int lane = threadIdx.x & 31;
    int warp = (blockIdx.x * blockDim.x + threadIdx.x) >> 5;
    int e0 = warp * 8;
    if (e0 >= NUM_EDGES) return;       // NUM_EDGES % 8 == 0

    const int t = lane & 3;
    const int g = lane >> 2;
    const int gbase = lane & ~3;
    const bool t0 = (t & 1) != 0;
    const bool t1 = (t & 2) != 0;

    // Dense weight loads: addr = e0*64B + lane*16B, contiguous 512B per instr.
    float4 m  = __ldg(&w_mean4[(size_t)e0 * 4 + lane]);
    float4 lv = __ldg(&w_lv4 [(size_t)e0 * 4 + lane]);
    float4 ep = __ldg(&eps_w4[(size_t)e0 * 4 + lane]);
    float4 vo;                          // v row i=t of edge e0+g (across j)
    vo.x = fmaf(ep.x, __expf(lv.x), m.x);
    vo.y = fmaf(ep.y, __expf(lv.y), m.y);
    vo.z = fmaf(ep.z, __expf(lv.z), m.z);
    vo.w = fmaf(ep.w, __expf(lv.w), m.w);

    // Indices: lanes 0-7 load rows (dst*4), lanes 8-15 load cols (src*4).
    int idxv = 0;
    if (lane < 8)       idxv = __ldg(&rows[(size_t)(e0 + lane) * 16]);
    else if (lane < 16) idxv = __ldg(&cols[(size_t)(e0 + lane - 8) * 16]);
    int dst4 = __shfl_sync(FULL, idxv, g);
    int src4 = __shfl_sync(FULL, idxv, 8 + g);

    // x row i=t of this edge's block: 2 float4 (both in the same 128B line).
    const float4* xr = reinterpret_cast<const float4*>(g_xt + (size_t)(src4 + t) * 8);
    float4 xr0 = __ldg(&xr[0]);     // batches 0-3 of row t
    float4 xr1 = __ldg(&xr[1]);     // batches 4-7 of row t

    // X[c] = x[row t][b=2c,2c+1]
    float2 X0 = make_float2(xr0.x, xr0.y);
    float2 X1 = make_float2(xr0.z, xr0.w);
    float2 X2 = make_float2(xr1.x, xr1.y);
    float2 X3 = make_float2(xr1.z, xr1.w);

    // Butterfly transpose within 4-lane group: lane t wants x[i][2t,2t+1].
    // send_k = X[t^k]; recv_k = x[row t^k][col t].
    float2 Xo = t1 ? (t0 ? X3 : X2) : (t0 ? X1 : X0);   // X[t]
    float2 s1 = t0 ? (t1 ? X2 : X0) : (t1 ? X3 : X1);   // X[t^1]
    float2 s2 = t1 ? (t0 ? X1 : X0) : (t0 ? X3 : X2);   // X[t^2]
    float2 s3 = t0 ? (t1 ? X0 : X2) : (t1 ? X1 : X3);   // X[t^3]
    float2 r1, r2, r3;
    r1.x = __shfl_xor_sync(FULL, s1.x, 1); r1.y = __shfl_xor_sync(FULL, s1.y, 1);
    r2.x = __shfl_xor_sync(FULL, s2.x, 2); r2.y = __shfl_xor_sync(FULL, s2.y, 2);
    r3.x = __shfl_xor_sync(FULL, s3.x, 3); r3.y = __shfl_xor_sync(FULL, s3.y, 3);

    // acc[j*2 + bb]: output j = 0..3 for batches 2t+bb.
    float acc[8];
#pragma unroll
    for (int k = 0; k < 8; k++) acc[k] = 0.0f;

#pragma unroll
    for (int i = 0; i < 4; i++) {
        int k = t ^ i;
        float2 xvi = (k == 0) ? Xo : (k == 1) ? r1 : (k == 2) ? r2 : r3;  // x[i][2t,2t+1]
        float vix = __shfl_sync(FULL, vo.x, gbase + i);   // v[i][0]
        float viy = __shfl_sync(FULL, vo.y, gbase + i);   // v[i][1]
        float viz = __shfl_sync(FULL, vo.z, gbase + i);   // v[i][2]
        float viw = __shfl_sync(FULL, vo.w, gbase + i);   // v[i][3]
        acc[0] = fmaf(vix, xvi.x, acc[0]);
        acc[1] = fmaf(vix, xvi.y, acc[1]);
        acc[2] = fmaf(viy, xvi.x, acc[2]);
        acc[3] = fmaf(viy, xvi.y, acc[3]);
        acc[4] = fmaf(viz, xvi.x, acc[4]);
        acc[5] = fmaf(viz, xvi.y, acc[5]);
        acc[6] = fmaf(viw, xvi.x, acc[6]);
        acc[7] = fmaf(viw, xvi.y, acc[7]);
    }

    // Transpose accumulators: A[j] = (out[j][2t], out[j][2t+1]) = column t of
    // the 4x4 (j x batch-pair) matrix. Lane t wants row j=t, all columns.
    float2 A0 = make_float2(acc[0], acc[1]);
    float2 A1 = make_float2(acc[2], acc[3]);
    float2 A2 = make_float2(acc[4], acc[5]);
    float2 A3 = make_float2(acc[6], acc[7]);
    float2 Ao = t1 ? (t0 ? A3 : A2) : (t0 ? A1 : A0);   // A[t]
    float2 a1 = t0 ? (t1 ? A2 : A0) : (t1 ? A3 : A1);   // A[t^1]
    float2 a2 = t1 ? (t0 ? A1 : A0) : (t0 ? A3 : A2);   // A[t^2]
    float2 a3 = t0 ? (t1 ? A0 : A2) : (t1 ? A1 : A3);   // A[t^3]
    float2 b1, b2, b3;
    b1.x = __shfl_xor_sync(FULL, a1.x, 1); b1.y = __shfl_xor_sync(FULL, a1.y, 1);
    b2.x = __shfl_xor_sync(FULL, a2.x, 2); b2.y = __shfl_xor_sync(FULL, a2.y, 2);
    b3.x = __shfl_xor_sync(FULL, a3.x, 3); b3.y = __shfl_xor_sync(FULL, a3.y, 3);

    // col_c = out[row t][b=2c,2c+1], c = t^k -> k = t^c
    float2 col[4];
#pragma unroll
    for (int c = 0; c < 4; c++) {
        int k = t ^ c;
        col[c] = (k == 0) ? Ao : (k == 1) ? b1 : (k == 2) ? b2 : b3;
    }

    // Edge's entire output row block: one 128B-aligned line in scratch.
    int e = e0 + g;
    float* qb = g_q + (size_t)(e & 1) * QCOPY + (size_t)(dst4 + t) * 8;
    asm volatile("red.global.add.v4.f32 [%0], {%1, %2, %3, %4};"
                 :: "l"(qb), "f"(col[0].x), "f"(col[0].y), "f"(col[1].x), "f"(col[1].y)
                 : "memory");
    asm volatile("red.global.add.v4.f32 [%0], {%1, %2, %3, %4};"
                 :: "l"(qb + 4), "f"(col[2].x), "f"(col[2].y), "f"(col[3].x), "f"(col[3].y)
                 : "memory");
}

// ---------------------------------------------------------------------------
// K3 (finalize): one thread per node s. Dense float4 reads of both scratch
// copies; bias computed once; 8 coalesced plane stores. Tail threads zero kl.
// ---------------------------------------------------------------------------
__global__ void __launch_bounds__(256)
finalize_kernel(const float* __restrict__ b_mean,
                const float* __restrict__ b_log_var,
                const float* __restrict__ eps_b,
                float* __restrict__ out, int out_size) {
    int idx = blockIdx.x * blockDim.x + threadIdx.x;
    if (idx < SIZE2) {
        int s = idx;
        const float4* q0 = reinterpret_cast<const float4*>(g_q + (size_t)s * 8);
        const float4* q1 = reinterpret_cast<const float4*>(g_q + QCOPY + (size_t)s * 8);
        float4 p0 = q0[0], p1 = q0[1];
        float4 c0 = q1[0], c1 = q1[1];
        float bias = fmaf(__ldg(&eps_b[s]), __expf(__ldg(&b_log_var[s])),
                          __ldg(&b_mean[s]));
        out[0 * SIZE2 + s] = p0.x + c0.x + bias;
        out[1 * SIZE2 + s] = p0.y + c0.y + bias;
        out[2 * SIZE2 + s] = p0.z + c0.z + bias;
        out[3 * SIZE2 + s] = p0.w + c0.w + bias;
        out[4 * SIZE2 + s] = p1.x + c1.x + bias;
        out[5 * SIZE2 + s] = p1.y + c1.y + bias;
        out[6 * SIZE2 + s] = p1.z + c1.z + bias;
        out[7 * SIZE2 + s] = p1.w + c1.w + bias;
    } else {
        int k = BATCH * SIZE2 + (idx - SIZE2);
        if (k < out_size) out[k] = 0.0f;   // kl = 0
    }
}

extern "C" void kernel_launch(void* const* d_in, const int* in_sizes, int n_in,
                              void* d_out, int out_size) {
    const float* x      = (const float*)d_in[0];
    const float* w_mean = (const float*)d_in[1];
    const float* w_lv   = (const float*)d_in[2];
    const float* b_mean = (const float*)d_in[3];
    const float* b_lv   = (const float*)d_in[4];
    const float* eps_w  = (const float*)d_in[5];
    const float* eps_b  = (const float*)d_in[6];
    const int*   rows   = (const int*)d_in[7];
    const int*   cols   = (const int*)d_in[8];
    float* out = (float*)d_out;

    int prep_n = (2 * QCOPY) / 4;                      // 320k zeroing threads
    if (prep_n < SIZE1 * 2) prep_n = SIZE1 * 2;
    prep_kernel<<<(prep_n + 255) / 256, 256>>>(x);

    spmm_edge_kernel<<<(NUM_EDGES / 8 * 32 + 255) / 256, 256>>>(
        (const float4*)w_mean, (const float4*)w_lv, (const float4*)eps_w,
        rows, cols);

    int fin_n = SIZE2 + 512;                           // nodes + kl tail
    finalize_kernel<<<(fin_n + 255) / 256, 256>>>(b_mean, b_lv, eps_b, out, out_size);
}